// round 3
// baseline (speedup 1.0000x reference)
#include <cuda_runtime.h>
#include <math.h>

// Problem constants (fixed by the dataset)
#define BDIM   768
#define HEADS  12
#define HD     64
#define BATCH  2
#define SEQ    2304          // 48*48
#define MTOT   (BATCH*SEQ)   // 4608
#define SCALEF 0.125f        // 64^-0.5

// Scratch (device globals — allocation-free)
__device__ float g_Q[BATCH*HEADS*SEQ*HD];   // [B,h,N,d]
__device__ float g_K[BATCH*HEADS*SEQ*HD];
__device__ float g_V[BATCH*HEADS*SEQ*HD];
__device__ float g_att[MTOT*BDIM];          // [B,N,C]

// ---------------------------------------------------------------------------
// GEMM 1: qkv = x @ qkv_w^T, scattered into Q/K/V  ([M=4608] x [F=2304] x K=768)
// Block tile 128x128, 256 threads, 8x8 per thread, K-step 8.
// ---------------------------------------------------------------------------
__global__ __launch_bounds__(256)
void qkv_gemm_kernel(const float* __restrict__ x, const float* __restrict__ w)
{
    __shared__ float As[8][132];
    __shared__ float Bs[8][132];

    const int tid = threadIdx.x;
    const int m0 = blockIdx.y * 128;
    const int f0 = blockIdx.x * 128;
    const int tx = tid & 15;       // 16 cols of threads
    const int ty = tid >> 4;       // 16 rows of threads

    const int lr = tid >> 1;           // 0..127
    const int lc = (tid & 1) * 4;      // 0 or 4
    const float* aptr = x + (size_t)(m0 + lr) * BDIM + lc;
    const float* bptr = w + (size_t)(f0 + lr) * BDIM + lc;

    float acc[8][8];
#pragma unroll
    for (int i = 0; i < 8; i++)
#pragma unroll
        for (int j = 0; j < 8; j++) acc[i][j] = 0.f;

    for (int k0 = 0; k0 < BDIM; k0 += 8) {
        float4 av = *(const float4*)(aptr + k0);
        float4 bv = *(const float4*)(bptr + k0);
        As[lc+0][lr] = av.x; As[lc+1][lr] = av.y; As[lc+2][lr] = av.z; As[lc+3][lr] = av.w;
        Bs[lc+0][lr] = bv.x; Bs[lc+1][lr] = bv.y; Bs[lc+2][lr] = bv.z; Bs[lc+3][lr] = bv.w;
        __syncthreads();
#pragma unroll
        for (int k = 0; k < 8; k++) {
            float a[8], b[8];
            *(float4*)(a)     = *(const float4*)&As[k][ty*8];
            *(float4*)(a + 4) = *(const float4*)&As[k][ty*8 + 4];
            *(float4*)(b)     = *(const float4*)&Bs[k][tx*8];
            *(float4*)(b + 4) = *(const float4*)&Bs[k][tx*8 + 4];
#pragma unroll
            for (int i = 0; i < 8; i++)
#pragma unroll
                for (int j = 0; j < 8; j++) acc[i][j] = fmaf(a[i], b[j], acc[i][j]);
        }
        __syncthreads();
    }

    // Scatter into Q/K/V with [B,h,N,d] layout
#pragma unroll
    for (int i = 0; i < 8; i++) {
        int m = m0 + ty*8 + i;
        int b = m / SEQ;
        int n = m - b * SEQ;
#pragma unroll
        for (int j = 0; j < 8; j++) {
            int f = f0 + tx*8 + j;
            int t = f / BDIM;                 // 0=q,1=k,2=v
            int rem = f - t * BDIM;
            int head = rem >> 6;
            int dd = rem & 63;
            float* dst = (t == 0) ? g_Q : ((t == 1) ? g_K : g_V);
            dst[(((size_t)(b*HEADS + head))*SEQ + n)*HD + dd] = acc[i][j];
        }
    }
}

// ---------------------------------------------------------------------------
// Flash attention: per (b,h), Br=Bc=64, online softmax, fp32
// grid (SEQ/64, B*HEADS), 256 threads.
// Dynamic smem = 3 * 64*64 * 4 = 49152 B (fits default limit, no attribute).
// Kt and Ps share one buffer (disjoint live ranges within a tile iteration).
// ---------------------------------------------------------------------------
__global__ __launch_bounds__(256)
void attn_kernel()
{
    extern __shared__ float sm[];
    float* Qt   = sm;              // [64][64]  Qt[dd][row]   (Q transposed)
    float* KtPs = sm + 64*64;      // [64][64]  Kt[dd][col] then Ps[row][col]
    float* Vs   = sm + 2*64*64;    // [64][64]  Vs[j][dd]

    const int tid = threadIdx.x;
    const int bh  = blockIdx.y;            // b*HEADS + head
    const int q0  = blockIdx.x * 64;
    const int tx = tid & 15, ty = tid >> 4;
    const int c0 = tx * 4, r0 = ty * 4;

    // Load Q tile transposed: Qt[dd][r]
    {
        const float* Qg = g_Q + ((size_t)bh * SEQ + q0) * HD;
        int r = tid >> 2;
        int c4 = (tid & 3) * 16;
#pragma unroll
        for (int u = 0; u < 4; u++) {
            float4 v = *(const float4*)(Qg + r*HD + c4 + 4*u);
            Qt[(c4+4*u+0)*64 + r] = v.x;
            Qt[(c4+4*u+1)*64 + r] = v.y;
            Qt[(c4+4*u+2)*64 + r] = v.z;
            Qt[(c4+4*u+3)*64 + r] = v.w;
        }
    }

    float o[4][4];
    float mrow[4], lrow[4];
#pragma unroll
    for (int i = 0; i < 4; i++) {
        mrow[i] = -1e30f; lrow[i] = 0.f;
#pragma unroll
        for (int j = 0; j < 4; j++) o[i][j] = 0.f;
    }

    const float* Kbase = g_K + (size_t)bh * SEQ * HD;
    const float* Vbase = g_V + (size_t)bh * SEQ * HD;

    for (int kt = 0; kt < SEQ; kt += 64) {
        __syncthreads();  // previous iteration done reading Ps(/Kt) and Vs
        // Load K tile transposed, V tile direct
        {
            const float* Kg = Kbase + (size_t)kt * HD;
            const float* Vg = Vbase + (size_t)kt * HD;
            int r = tid >> 2;
            int c4 = (tid & 3) * 16;
#pragma unroll
            for (int u = 0; u < 4; u++) {
                float4 kv = *(const float4*)(Kg + r*HD + c4 + 4*u);
                KtPs[(c4+4*u+0)*64 + r] = kv.x;
                KtPs[(c4+4*u+1)*64 + r] = kv.y;
                KtPs[(c4+4*u+2)*64 + r] = kv.z;
                KtPs[(c4+4*u+3)*64 + r] = kv.w;
                float4 vv = *(const float4*)(Vg + r*HD + c4 + 4*u);
                *(float4*)&Vs[r*64 + c4 + 4*u] = vv;
            }
        }
        __syncthreads();

        // S = Q K^T * scale  (4x4 per thread)
        float s[4][4];
#pragma unroll
        for (int i = 0; i < 4; i++)
#pragma unroll
            for (int j = 0; j < 4; j++) s[i][j] = 0.f;

#pragma unroll 8
        for (int dd = 0; dd < 64; dd++) {
            float4 a = *(const float4*)&Qt[dd*64 + r0];
            float4 b = *(const float4*)&KtPs[dd*64 + c0];
            float av[4] = {a.x, a.y, a.z, a.w};
            float bv[4] = {b.x, b.y, b.z, b.w};
#pragma unroll
            for (int i = 0; i < 4; i++)
#pragma unroll
                for (int j = 0; j < 4; j++) s[i][j] = fmaf(av[i], bv[j], s[i][j]);
        }
        __syncthreads();   // everyone done reading Kt before P overwrites it

        // Online softmax per row; write P (row-major, float4) into KtPs
#pragma unroll
        for (int i = 0; i < 4; i++) {
            float rm = fmaxf(fmaxf(s[i][0], s[i][1]), fmaxf(s[i][2], s[i][3])) * SCALEF;
#pragma unroll
            for (int off = 1; off < 16; off <<= 1)
                rm = fmaxf(rm, __shfl_xor_sync(0xffffffffu, rm, off));
            float mnew = fmaxf(mrow[i], rm);
            float alpha = __expf(mrow[i] - mnew);
            mrow[i] = mnew;
            float4 p4;
            p4.x = __expf(s[i][0]*SCALEF - mnew);
            p4.y = __expf(s[i][1]*SCALEF - mnew);
            p4.z = __expf(s[i][2]*SCALEF - mnew);
            p4.w = __expf(s[i][3]*SCALEF - mnew);
            *(float4*)&KtPs[(r0+i)*64 + c0] = p4;
            float rs = p4.x + p4.y + p4.z + p4.w;
#pragma unroll
            for (int off = 1; off < 16; off <<= 1)
                rs += __shfl_xor_sync(0xffffffffu, rs, off);
            lrow[i] = lrow[i]*alpha + rs;
#pragma unroll
            for (int j = 0; j < 4; j++) o[i][j] *= alpha;
        }
        __syncthreads();

        // O += P @ V   (P read row-major as float4 along j)
#pragma unroll 4
        for (int j0 = 0; j0 < 64; j0 += 4) {
            float4 p[4];
#pragma unroll
            for (int i = 0; i < 4; i++)
                p[i] = *(const float4*)&KtPs[(r0+i)*64 + j0];
#pragma unroll
            for (int jj = 0; jj < 4; jj++) {
                float4 v = *(const float4*)&Vs[(j0+jj)*64 + c0];
                float pv[4] = {p[0].x, p[1].x, p[2].x, p[3].x};
                // select jj-th component of each p[i]
                pv[0] = (jj==0)?p[0].x:(jj==1)?p[0].y:(jj==2)?p[0].z:p[0].w;
                pv[1] = (jj==0)?p[1].x:(jj==1)?p[1].y:(jj==2)?p[1].z:p[1].w;
                pv[2] = (jj==0)?p[2].x:(jj==1)?p[2].y:(jj==2)?p[2].z:p[2].w;
                pv[3] = (jj==0)?p[3].x:(jj==1)?p[3].y:(jj==2)?p[3].z:p[3].w;
                float vv[4] = {v.x, v.y, v.z, v.w};
#pragma unroll
                for (int i = 0; i < 4; i++)
#pragma unroll
                    for (int c = 0; c < 4; c++) o[i][c] = fmaf(pv[i], vv[c], o[i][c]);
            }
        }
    }

    // Epilogue: write [B,N,C] with C = head*64 + dd
    const int b = bh / HEADS;
    const int head = bh - b * HEADS;
#pragma unroll
    for (int i = 0; i < 4; i++) {
        int n = q0 + r0 + i;
        float inv = 1.0f / lrow[i];
        float4 w;
        w.x = o[i][0]*inv; w.y = o[i][1]*inv; w.z = o[i][2]*inv; w.w = o[i][3]*inv;
        *(float4*)&g_att[((size_t)(b*SEQ + n))*BDIM + head*HD + c0] = w;
    }
}

// ---------------------------------------------------------------------------
// GEMM 2: out = att @ proj_w^T + proj_b   ([M=4608] x [F=768] x K=768)
// ---------------------------------------------------------------------------
__global__ __launch_bounds__(256)
void proj_gemm_kernel(const float* __restrict__ w, const float* __restrict__ bias,
                      float* __restrict__ out)
{
    __shared__ float As[8][132];
    __shared__ float Bs[8][132];

    const int tid = threadIdx.x;
    const int m0 = blockIdx.y * 128;
    const int f0 = blockIdx.x * 128;
    const int tx = tid & 15;
    const int ty = tid >> 4;

    const int lr = tid >> 1;
    const int lc = (tid & 1) * 4;
    const float* aptr = g_att + (size_t)(m0 + lr) * BDIM + lc;
    const float* bptr = w + (size_t)(f0 + lr) * BDIM + lc;

    float acc[8][8];
#pragma unroll
    for (int i = 0; i < 8; i++)
#pragma unroll
        for (int j = 0; j < 8; j++) acc[i][j] = 0.f;

    for (int k0 = 0; k0 < BDIM; k0 += 8) {
        float4 av = *(const float4*)(aptr + k0);
        float4 bv = *(const float4*)(bptr + k0);
        As[lc+0][lr] = av.x; As[lc+1][lr] = av.y; As[lc+2][lr] = av.z; As[lc+3][lr] = av.w;
        Bs[lc+0][lr] = bv.x; Bs[lc+1][lr] = bv.y; Bs[lc+2][lr] = bv.z; Bs[lc+3][lr] = bv.w;
        __syncthreads();
#pragma unroll
        for (int k = 0; k < 8; k++) {
            float a[8], b[8];
            *(float4*)(a)     = *(const float4*)&As[k][ty*8];
            *(float4*)(a + 4) = *(const float4*)&As[k][ty*8 + 4];
            *(float4*)(b)     = *(const float4*)&Bs[k][tx*8];
            *(float4*)(b + 4) = *(const float4*)&Bs[k][tx*8 + 4];
#pragma unroll
            for (int i = 0; i < 8; i++)
#pragma unroll
                for (int j = 0; j < 8; j++) acc[i][j] = fmaf(a[i], b[j], acc[i][j]);
        }
        __syncthreads();
    }

#pragma unroll
    for (int i = 0; i < 8; i++) {
        int m = m0 + ty*8 + i;
#pragma unroll
        for (int j = 0; j < 8; j++) {
            int f = f0 + tx*8 + j;
            out[(size_t)m * BDIM + f] = acc[i][j] + __ldg(&bias[f]);
        }
    }
}

// ---------------------------------------------------------------------------
extern "C" void kernel_launch(void* const* d_in, const int* in_sizes, int n_in,
                              void* d_out, int out_size)
{
    const float* x      = (const float*)d_in[0];
    // d_in[1] = H, d_in[2] = W (ints, fixed 48x48 — unused)
    const float* qkv_w  = (const float*)d_in[3];
    const float* proj_w = (const float*)d_in[4];
    const float* proj_b = (const float*)d_in[5];
    float* out = (float*)d_out;

    const int ATTN_SMEM = 3 * 64 * 64 * sizeof(float);  // 49152 B = default limit

    dim3 g1(2304/128, MTOT/128);   // 18 x 36
    qkv_gemm_kernel<<<g1, 256>>>(x, qkv_w);

    dim3 g2(SEQ/64, BATCH*HEADS);  // 36 x 24
    attn_kernel<<<g2, 256, ATTN_SMEM>>>();

    dim3 g3(BDIM/128, MTOT/128);   // 6 x 36
    proj_gemm_kernel<<<g3, 256>>>(proj_w, proj_b, out);
}

// round 4
// speedup vs baseline: 1.1069x; 1.1069x over previous
#include <cuda_runtime.h>
#include <math.h>

// Problem constants (fixed by the dataset)
#define BDIM   768
#define HEADS  12
#define HD     64
#define BATCH  2
#define SEQ    2304          // 48*48
#define MTOT   (BATCH*SEQ)   // 4608
#define SCALEF 0.125f        // 64^-0.5

typedef unsigned long long u64;

// ---- packed f32x2 helpers (sm_103a) ---------------------------------------
__device__ __forceinline__ u64 pack2(float x, float y) {
    u64 r; asm("mov.b64 %0,{%1,%2};" : "=l"(r) : "f"(x), "f"(y)); return r;
}
__device__ __forceinline__ u64 dup2(float x) { return pack2(x, x); }
__device__ __forceinline__ void unpack2(u64 p, float& x, float& y) {
    asm("mov.b64 {%0,%1},%2;" : "=f"(x), "=f"(y) : "l"(p));
}
__device__ __forceinline__ void ffma2(u64& d, u64 a, u64 b) {
    asm("fma.rn.f32x2 %0,%1,%2,%0;" : "+l"(d) : "l"(a), "l"(b));
}
__device__ __forceinline__ void fmul2(u64& d, u64 a) {
    asm("mul.rn.f32x2 %0,%0,%1;" : "+l"(d) : "l"(a));
}
__device__ __forceinline__ void fadd2(u64& d, u64 a) {
    asm("add.rn.f32x2 %0,%0,%1;" : "+l"(d) : "l"(a));
}

// Scratch (device globals — allocation-free)
__device__ float g_Q[BATCH*HEADS*SEQ*HD];   // [B,h,N,d]
__device__ float g_K[BATCH*HEADS*SEQ*HD];
__device__ float g_V[BATCH*HEADS*SEQ*HD];
__device__ float g_att[MTOT*BDIM];          // [B,N,C]

// ---------------------------------------------------------------------------
// GEMM 1: qkv = x @ qkv_w^T, scattered into Q/K/V  ([M=4608] x [F=2304] x K=768)
// Block tile 128x128, 256 threads, 8x8 per thread (paired as 8x4 f32x2), K-step 8.
// ---------------------------------------------------------------------------
__global__ __launch_bounds__(256)
void qkv_gemm_kernel(const float* __restrict__ x, const float* __restrict__ w)
{
    __shared__ float As[8][132];
    __shared__ float Bs[8][132];

    const int tid = threadIdx.x;
    const int m0 = blockIdx.y * 128;
    const int f0 = blockIdx.x * 128;
    const int tx = tid & 15;       // 16 cols of threads
    const int ty = tid >> 4;       // 16 rows of threads

    const int lr = tid >> 1;           // 0..127
    const int lc = (tid & 1) * 4;      // 0 or 4
    const float* aptr = x + (size_t)(m0 + lr) * BDIM + lc;
    const float* bptr = w + (size_t)(f0 + lr) * BDIM + lc;

    u64 acc2[8][4];
#pragma unroll
    for (int i = 0; i < 8; i++)
#pragma unroll
        for (int jp = 0; jp < 4; jp++) acc2[i][jp] = 0ull;

    float4 av = *(const float4*)(aptr);
    float4 bv = *(const float4*)(bptr);

    for (int k0 = 0; k0 < BDIM; k0 += 8) {
        As[lc+0][lr] = av.x; As[lc+1][lr] = av.y; As[lc+2][lr] = av.z; As[lc+3][lr] = av.w;
        Bs[lc+0][lr] = bv.x; Bs[lc+1][lr] = bv.y; Bs[lc+2][lr] = bv.z; Bs[lc+3][lr] = bv.w;
        __syncthreads();
        if (k0 + 8 < BDIM) {               // prefetch next K-tile (overlaps compute)
            av = *(const float4*)(aptr + k0 + 8);
            bv = *(const float4*)(bptr + k0 + 8);
        }
#pragma unroll
        for (int k = 0; k < 8; k++) {
            float a[8];
            *(float4*)(a)     = *(const float4*)&As[k][ty*8];
            *(float4*)(a + 4) = *(const float4*)&As[k][ty*8 + 4];
            ulonglong2 blo = *(const ulonglong2*)&Bs[k][tx*8];
            ulonglong2 bhi = *(const ulonglong2*)&Bs[k][tx*8 + 4];
            u64 b2[4] = {blo.x, blo.y, bhi.x, bhi.y};
#pragma unroll
            for (int i = 0; i < 8; i++) {
                u64 a2 = dup2(a[i]);
#pragma unroll
                for (int jp = 0; jp < 4; jp++) ffma2(acc2[i][jp], a2, b2[jp]);
            }
        }
        __syncthreads();
    }

    // Scatter into Q/K/V with [B,h,N,d] layout (64-bit stores: dd is even)
#pragma unroll
    for (int i = 0; i < 8; i++) {
        int m = m0 + ty*8 + i;
        int b = m / SEQ;
        int n = m - b * SEQ;
#pragma unroll
        for (int jp = 0; jp < 4; jp++) {
            int f = f0 + tx*8 + 2*jp;
            int t = f / BDIM;                 // 0=q,1=k,2=v
            int rem = f - t * BDIM;
            int head = rem >> 6;
            int dd = rem & 63;                // even
            float* dst = (t == 0) ? g_Q : ((t == 1) ? g_K : g_V);
            *(u64*)&dst[(((size_t)(b*HEADS + head))*SEQ + n)*HD + dd] = acc2[i][jp];
        }
    }
}

// ---------------------------------------------------------------------------
// Flash attention: per (b,h), Br=Bc=64, online softmax, fp32 (f32x2 packed)
// grid (SEQ/64, B*HEADS), 256 threads.  Dynamic smem = 49152 B.
// Kt and Ps share one buffer (disjoint live ranges within a tile iteration).
// ---------------------------------------------------------------------------
__global__ __launch_bounds__(256)
void attn_kernel()
{
    extern __shared__ float sm[];
    float* Qt   = sm;              // [64][64]  Qt[dd][row]   (Q transposed)
    float* KtPs = sm + 64*64;      // [64][64]  Kt[dd][col] then Ps[row][col]
    float* Vs   = sm + 2*64*64;    // [64][64]  Vs[j][dd]

    const int tid = threadIdx.x;
    const int bh  = blockIdx.y;            // b*HEADS + head
    const int q0  = blockIdx.x * 64;
    const int tx = tid & 15, ty = tid >> 4;
    const int c0 = tx * 4, r0 = ty * 4;

    // Load Q tile transposed: Qt[dd][r]
    {
        const float* Qg = g_Q + ((size_t)bh * SEQ + q0) * HD;
        int r = tid >> 2;
        int c4 = (tid & 3) * 16;
#pragma unroll
        for (int u = 0; u < 4; u++) {
            float4 v = *(const float4*)(Qg + r*HD + c4 + 4*u);
            Qt[(c4+4*u+0)*64 + r] = v.x;
            Qt[(c4+4*u+1)*64 + r] = v.y;
            Qt[(c4+4*u+2)*64 + r] = v.z;
            Qt[(c4+4*u+3)*64 + r] = v.w;
        }
    }

    u64 o2[4][2];                 // output accum, pairs along c
    float mrow[4], lrow[4];
#pragma unroll
    for (int i = 0; i < 4; i++) {
        mrow[i] = -1e30f; lrow[i] = 0.f;
        o2[i][0] = 0ull; o2[i][1] = 0ull;
    }

    const float* Kbase = g_K + (size_t)bh * SEQ * HD;
    const float* Vbase = g_V + (size_t)bh * SEQ * HD;

    for (int kt = 0; kt < SEQ; kt += 64) {
        __syncthreads();  // prev iter done reading Ps(/Kt) and Vs
        // Load K tile transposed, V tile direct
        {
            const float* Kg = Kbase + (size_t)kt * HD;
            const float* Vg = Vbase + (size_t)kt * HD;
            int r = tid >> 2;
            int c4 = (tid & 3) * 16;
#pragma unroll
            for (int u = 0; u < 4; u++) {
                float4 kv = *(const float4*)(Kg + r*HD + c4 + 4*u);
                KtPs[(c4+4*u+0)*64 + r] = kv.x;
                KtPs[(c4+4*u+1)*64 + r] = kv.y;
                KtPs[(c4+4*u+2)*64 + r] = kv.z;
                KtPs[(c4+4*u+3)*64 + r] = kv.w;
                float4 vv = *(const float4*)(Vg + r*HD + c4 + 4*u);
                *(float4*)&Vs[r*64 + c4 + 4*u] = vv;
            }
        }
        __syncthreads();

        // S = Q K^T (4 rows x 2 col-pairs per thread, f32x2)
        u64 s2[4][2];
#pragma unroll
        for (int i = 0; i < 4; i++) { s2[i][0] = 0ull; s2[i][1] = 0ull; }

#pragma unroll 8
        for (int dd = 0; dd < 64; dd++) {
            float4 a = *(const float4*)&Qt[dd*64 + r0];
            ulonglong2 b = *(const ulonglong2*)&KtPs[dd*64 + c0];
            float aa[4] = {a.x, a.y, a.z, a.w};
#pragma unroll
            for (int i = 0; i < 4; i++) {
                u64 a2 = dup2(aa[i]);
                ffma2(s2[i][0], a2, b.x);
                ffma2(s2[i][1], a2, b.y);
            }
        }
        __syncthreads();   // everyone done reading Kt before P overwrites it

        // Online softmax per row; write P (row-major, float4) into KtPs
#pragma unroll
        for (int i = 0; i < 4; i++) {
            float s0, s1, sA, sB;
            unpack2(s2[i][0], s0, s1);
            unpack2(s2[i][1], sA, sB);
            float rm = fmaxf(fmaxf(s0, s1), fmaxf(sA, sB)) * SCALEF;
#pragma unroll
            for (int off = 1; off < 16; off <<= 1)
                rm = fmaxf(rm, __shfl_xor_sync(0xffffffffu, rm, off));
            float mnew = fmaxf(mrow[i], rm);
            float alpha = __expf(mrow[i] - mnew);
            mrow[i] = mnew;
            float4 p4;
            p4.x = __expf(s0*SCALEF - mnew);
            p4.y = __expf(s1*SCALEF - mnew);
            p4.z = __expf(sA*SCALEF - mnew);
            p4.w = __expf(sB*SCALEF - mnew);
            *(float4*)&KtPs[(r0+i)*64 + c0] = p4;
            float rs = (p4.x + p4.y) + (p4.z + p4.w);
#pragma unroll
            for (int off = 1; off < 16; off <<= 1)
                rs += __shfl_xor_sync(0xffffffffu, rs, off);
            lrow[i] = lrow[i]*alpha + rs;
            u64 al = dup2(alpha);
            fmul2(o2[i][0], al);
            fmul2(o2[i][1], al);
        }
        __syncthreads();

        // O += P @ V   (f32x2 along c)
#pragma unroll 4
        for (int j0 = 0; j0 < 64; j0 += 4) {
            float prow[4][4];
#pragma unroll
            for (int i = 0; i < 4; i++)
                *(float4*)prow[i] = *(const float4*)&KtPs[(r0+i)*64 + j0];
#pragma unroll
            for (int jj = 0; jj < 4; jj++) {
                ulonglong2 v = *(const ulonglong2*)&Vs[(j0+jj)*64 + c0];
#pragma unroll
                for (int i = 0; i < 4; i++) {
                    u64 pd = dup2(prow[i][jj]);
                    ffma2(o2[i][0], pd, v.x);
                    ffma2(o2[i][1], pd, v.y);
                }
            }
        }
    }

    // Epilogue: write [B,N,C] with C = head*64 + dd  (128-bit stores)
    const int b = bh / HEADS;
    const int head = bh - b * HEADS;
#pragma unroll
    for (int i = 0; i < 4; i++) {
        int n = q0 + r0 + i;
        u64 iv = dup2(1.0f / lrow[i]);
        fmul2(o2[i][0], iv);
        fmul2(o2[i][1], iv);
        ulonglong2 st; st.x = o2[i][0]; st.y = o2[i][1];
        *(ulonglong2*)&g_att[((size_t)(b*SEQ + n))*BDIM + head*HD + c0] = st;
    }
}

// ---------------------------------------------------------------------------
// GEMM 2: out = att @ proj_w^T + proj_b   ([M=4608] x [F=768] x K=768)
// ---------------------------------------------------------------------------
__global__ __launch_bounds__(256)
void proj_gemm_kernel(const float* __restrict__ w, const float* __restrict__ bias,
                      float* __restrict__ out)
{
    __shared__ float As[8][132];
    __shared__ float Bs[8][132];

    const int tid = threadIdx.x;
    const int m0 = blockIdx.y * 128;
    const int f0 = blockIdx.x * 128;
    const int tx = tid & 15;
    const int ty = tid >> 4;

    const int lr = tid >> 1;
    const int lc = (tid & 1) * 4;
    const float* aptr = g_att + (size_t)(m0 + lr) * BDIM + lc;
    const float* bptr = w + (size_t)(f0 + lr) * BDIM + lc;

    u64 acc2[8][4];
#pragma unroll
    for (int i = 0; i < 8; i++)
#pragma unroll
        for (int jp = 0; jp < 4; jp++) acc2[i][jp] = 0ull;

    float4 av = *(const float4*)(aptr);
    float4 bv = *(const float4*)(bptr);

    for (int k0 = 0; k0 < BDIM; k0 += 8) {
        As[lc+0][lr] = av.x; As[lc+1][lr] = av.y; As[lc+2][lr] = av.z; As[lc+3][lr] = av.w;
        Bs[lc+0][lr] = bv.x; Bs[lc+1][lr] = bv.y; Bs[lc+2][lr] = bv.z; Bs[lc+3][lr] = bv.w;
        __syncthreads();
        if (k0 + 8 < BDIM) {
            av = *(const float4*)(aptr + k0 + 8);
            bv = *(const float4*)(bptr + k0 + 8);
        }
#pragma unroll
        for (int k = 0; k < 8; k++) {
            float a[8];
            *(float4*)(a)     = *(const float4*)&As[k][ty*8];
            *(float4*)(a + 4) = *(const float4*)&As[k][ty*8 + 4];
            ulonglong2 blo = *(const ulonglong2*)&Bs[k][tx*8];
            ulonglong2 bhi = *(const ulonglong2*)&Bs[k][tx*8 + 4];
            u64 b2[4] = {blo.x, blo.y, bhi.x, bhi.y};
#pragma unroll
            for (int i = 0; i < 8; i++) {
                u64 a2 = dup2(a[i]);
#pragma unroll
                for (int jp = 0; jp < 4; jp++) ffma2(acc2[i][jp], a2, b2[jp]);
            }
        }
        __syncthreads();
    }

    // Epilogue: add bias (pairs), 128-bit stores
    u64 bias2[4];
#pragma unroll
    for (int jp = 0; jp < 4; jp++)
        bias2[jp] = *(const u64*)&bias[f0 + tx*8 + 2*jp];

#pragma unroll
    for (int i = 0; i < 8; i++) {
        int m = m0 + ty*8 + i;
#pragma unroll
        for (int jp = 0; jp < 4; jp++) fadd2(acc2[i][jp], bias2[jp]);
        ulonglong2 lo; lo.x = acc2[i][0]; lo.y = acc2[i][1];
        ulonglong2 hi; hi.x = acc2[i][2]; hi.y = acc2[i][3];
        *(ulonglong2*)&out[(size_t)m * BDIM + f0 + tx*8]     = lo;
        *(ulonglong2*)&out[(size_t)m * BDIM + f0 + tx*8 + 4] = hi;
    }
}

// ---------------------------------------------------------------------------
extern "C" void kernel_launch(void* const* d_in, const int* in_sizes, int n_in,
                              void* d_out, int out_size)
{
    const float* x      = (const float*)d_in[0];
    // d_in[1] = H, d_in[2] = W (ints, fixed 48x48 — unused)
    const float* qkv_w  = (const float*)d_in[3];
    const float* proj_w = (const float*)d_in[4];
    const float* proj_b = (const float*)d_in[5];
    float* out = (float*)d_out;

    const int ATTN_SMEM = 3 * 64 * 64 * sizeof(float);  // 49152 B = default limit

    dim3 g1(2304/128, MTOT/128);   // 18 x 36
    qkv_gemm_kernel<<<g1, 256>>>(x, qkv_w);

    dim3 g2(SEQ/64, BATCH*HEADS);  // 36 x 24
    attn_kernel<<<g2, 256, ATTN_SMEM>>>();

    dim3 g3(BDIM/128, MTOT/128);   // 6 x 36
    proj_gemm_kernel<<<g3, 256>>>(proj_w, proj_b, out);
}

// round 12
// speedup vs baseline: 1.2810x; 1.1573x over previous
#include <cuda_runtime.h>
#include <cstdint>
#include <math.h>

// Problem constants (fixed by the dataset)
#define BDIM   768
#define HEADS  12
#define HD     64
#define BATCH  2
#define SEQ    2304          // 48*48
#define MTOT   (BATCH*SEQ)   // 4608
#define SCALEF 0.125f        // 64^-0.5

typedef unsigned long long u64;

// ---- packed f32x2 helpers (sm_103a) ---------------------------------------
__device__ __forceinline__ u64 pack2(float x, float y) {
    u64 r; asm("mov.b64 %0,{%1,%2};" : "=l"(r) : "f"(x), "f"(y)); return r;
}
__device__ __forceinline__ u64 dup2(float x) { return pack2(x, x); }
__device__ __forceinline__ void unpack2(u64 p, float& x, float& y) {
    asm("mov.b64 {%0,%1},%2;" : "=f"(x), "=f"(y) : "l"(p));
}
__device__ __forceinline__ void ffma2(u64& d, u64 a, u64 b) {
    asm("fma.rn.f32x2 %0,%1,%2,%0;" : "+l"(d) : "l"(a), "l"(b));
}
__device__ __forceinline__ void fmul2(u64& d, u64 a) {
    asm("mul.rn.f32x2 %0,%0,%1;" : "+l"(d) : "l"(a));
}
__device__ __forceinline__ void fadd2(u64& d, u64 a) {
    asm("add.rn.f32x2 %0,%0,%1;" : "+l"(d) : "l"(a));
}

// ---- tf32 mma helpers -----------------------------------------------------
__device__ __forceinline__ uint32_t to_tf32(float x) {
    uint32_t r; asm("cvt.rna.tf32.f32 %0, %1;" : "=r"(r) : "f"(x)); return r;
}
__device__ __forceinline__ void mma_tf32(float* c, const uint32_t* a,
                                         uint32_t b0, uint32_t b1) {
    asm volatile(
        "mma.sync.aligned.m16n8k8.row.col.f32.tf32.tf32.f32 "
        "{%0,%1,%2,%3}, {%4,%5,%6,%7}, {%8,%9}, {%0,%1,%2,%3};"
        : "+f"(c[0]), "+f"(c[1]), "+f"(c[2]), "+f"(c[3])
        : "r"(a[0]), "r"(a[1]), "r"(a[2]), "r"(a[3]), "r"(b0), "r"(b1));
}

// Scratch (device globals — allocation-free)
__device__ float g_Q[BATCH*HEADS*SEQ*HD];   // [B,h,N,d]
__device__ float g_K[BATCH*HEADS*SEQ*HD];
__device__ float g_V[BATCH*HEADS*SEQ*HD];
__device__ float g_att[MTOT*BDIM];          // [B,N,C]

// ===========================================================================
// qkv GEMM (tf32 mma.sync): D[m][f] = sum_k x[m][k] * qkv_w[f][k], K=768.
// CTA 128x128, 256 threads = 8 warps (2m x 4n); warp tile 64x32.
// K-chunks of 16, double-buffered smem (stride 20 words), scatter to Q/K/V.
// ===========================================================================
__global__ __launch_bounds__(256)
void qkv_mma_kernel(const float* __restrict__ A, const float* __restrict__ W)
{
    __shared__ uint32_t As[2][128 * 20];
    __shared__ uint32_t Bs[2][128 * 20];

    const int tid  = threadIdx.x;
    const int lane = tid & 31;
    const int wid  = tid >> 5;
    const int quad = lane >> 2;      // 0..7
    const int tq   = lane & 3;       // 0..3
    const int wm   = wid >> 2;       // 0..1
    const int wn   = wid & 3;        // 0..3
    const int m0   = blockIdx.y * 128;
    const int f0   = blockIdx.x * 128;

    const int rowL = tid >> 1;           // 0..127
    const int cb   = (tid & 1) * 8;      // 0 or 8
    const float* Ap = A + (size_t)(m0 + rowL) * BDIM + cb;
    const float* Wp = W + (size_t)(f0 + rowL) * BDIM + cb;

    float acc[4][4][4];
#pragma unroll
    for (int mi = 0; mi < 4; mi++)
#pragma unroll
        for (int ni = 0; ni < 4; ni++)
#pragma unroll
            for (int r = 0; r < 4; r++) acc[mi][ni][r] = 0.f;

    float4 pa0 = *(const float4*)(Ap);
    float4 pa1 = *(const float4*)(Ap + 4);
    float4 pb0 = *(const float4*)(Wp);
    float4 pb1 = *(const float4*)(Wp + 4);

#define NCHUNK 48
    for (int c = 0; c < NCHUNK; c++) {
        const int buf = c & 1;
        {
            uint4 t0, t1;
            t0.x = to_tf32(pa0.x); t0.y = to_tf32(pa0.y);
            t0.z = to_tf32(pa0.z); t0.w = to_tf32(pa0.w);
            t1.x = to_tf32(pa1.x); t1.y = to_tf32(pa1.y);
            t1.z = to_tf32(pa1.z); t1.w = to_tf32(pa1.w);
            *(uint4*)&As[buf][rowL * 20 + cb]     = t0;
            *(uint4*)&As[buf][rowL * 20 + cb + 4] = t1;
            t0.x = to_tf32(pb0.x); t0.y = to_tf32(pb0.y);
            t0.z = to_tf32(pb0.z); t0.w = to_tf32(pb0.w);
            t1.x = to_tf32(pb1.x); t1.y = to_tf32(pb1.y);
            t1.z = to_tf32(pb1.z); t1.w = to_tf32(pb1.w);
            *(uint4*)&Bs[buf][rowL * 20 + cb]     = t0;
            *(uint4*)&Bs[buf][rowL * 20 + cb + 4] = t1;
        }
        __syncthreads();
        if (c + 1 < NCHUNK) {
            const int k0 = (c + 1) * 16;
            pa0 = *(const float4*)(Ap + k0);
            pa1 = *(const float4*)(Ap + k0 + 4);
            pb0 = *(const float4*)(Wp + k0);
            pb1 = *(const float4*)(Wp + k0 + 4);
        }
#pragma unroll
        for (int ks = 0; ks < 2; ks++) {
            uint32_t af[4][4];
#pragma unroll
            for (int mi = 0; mi < 4; mi++) {
                const int rr = wm * 64 + mi * 16 + quad;
                af[mi][0] = As[buf][rr * 20 + ks * 8 + tq];
                af[mi][1] = As[buf][(rr + 8) * 20 + ks * 8 + tq];
                af[mi][2] = As[buf][rr * 20 + ks * 8 + tq + 4];
                af[mi][3] = As[buf][(rr + 8) * 20 + ks * 8 + tq + 4];
            }
#pragma unroll
            for (int ni = 0; ni < 4; ni++) {
                const int cc = wn * 32 + ni * 8 + quad;
                uint32_t b0 = Bs[buf][cc * 20 + ks * 8 + tq];
                uint32_t b1 = Bs[buf][cc * 20 + ks * 8 + tq + 4];
#pragma unroll
                for (int mi = 0; mi < 4; mi++)
                    mma_tf32(acc[mi][ni], af[mi], b0, b1);
            }
        }
        __syncthreads();
    }

    // Epilogue: scatter into Q/K/V ([B,h,N,d]); thread owns rows quad/quad+8,
    // col pair 2*tq within each 8-wide n tile.
#pragma unroll
    for (int mi = 0; mi < 4; mi++) {
#pragma unroll
        for (int ni = 0; ni < 4; ni++) {
            const int m = m0 + wm * 64 + mi * 16 + quad;
            const int f = f0 + wn * 32 + ni * 8 + 2 * tq;
            const int t    = f / BDIM;
            const int rem  = f - t * BDIM;
            const int head = rem >> 6;
            const int dd   = rem & 63;
            float* dst = (t == 0) ? g_Q : ((t == 1) ? g_K : g_V);
#pragma unroll
            for (int h = 0; h < 2; h++) {
                const int mm = m + 8 * h;
                const int b  = mm / SEQ;
                const int n  = mm - b * SEQ;
                float2 v; v.x = acc[mi][ni][2*h]; v.y = acc[mi][ni][2*h+1];
                *(float2*)&dst[(((size_t)(b * HEADS + head)) * SEQ + n) * HD + dd] = v;
            }
        }
    }
}

// ---------------------------------------------------------------------------
// Flash attention: per (b,h), Br=Bc=64, online softmax, fp32 (f32x2 packed)
// grid (SEQ/64, B*HEADS), 256 threads.  Dynamic smem = 49152 B.
// (VERIFIED round-4 version, unchanged.)
// ---------------------------------------------------------------------------
__global__ __launch_bounds__(256)
void attn_kernel()
{
    extern __shared__ float sm[];
    float* Qt   = sm;              // [64][64]  Qt[dd][row]
    float* KtPs = sm + 64*64;      // [64][64]  Kt[dd][col] then Ps[row][col]
    float* Vs   = sm + 2*64*64;    // [64][64]  Vs[j][dd]

    const int tid = threadIdx.x;
    const int bh  = blockIdx.y;
    const int q0  = blockIdx.x * 64;
    const int tx = tid & 15, ty = tid >> 4;
    const int c0 = tx * 4, r0 = ty * 4;

    {
        const float* Qg = g_Q + ((size_t)bh * SEQ + q0) * HD;
        int r = tid >> 2;
        int c4 = (tid & 3) * 16;
#pragma unroll
        for (int u = 0; u < 4; u++) {
            float4 v = *(const float4*)(Qg + r*HD + c4 + 4*u);
            Qt[(c4+4*u+0)*64 + r] = v.x;
            Qt[(c4+4*u+1)*64 + r] = v.y;
            Qt[(c4+4*u+2)*64 + r] = v.z;
            Qt[(c4+4*u+3)*64 + r] = v.w;
        }
    }

    u64 o2[4][2];
    float mrow[4], lrow[4];
#pragma unroll
    for (int i = 0; i < 4; i++) {
        mrow[i] = -1e30f; lrow[i] = 0.f;
        o2[i][0] = 0ull; o2[i][1] = 0ull;
    }

    const float* Kbase = g_K + (size_t)bh * SEQ * HD;
    const float* Vbase = g_V + (size_t)bh * SEQ * HD;

    for (int kt = 0; kt < SEQ; kt += 64) {
        __syncthreads();
        {
            const float* Kg = Kbase + (size_t)kt * HD;
            const float* Vg = Vbase + (size_t)kt * HD;
            int r = tid >> 2;
            int c4 = (tid & 3) * 16;
#pragma unroll
            for (int u = 0; u < 4; u++) {
                float4 kv = *(const float4*)(Kg + r*HD + c4 + 4*u);
                KtPs[(c4+4*u+0)*64 + r] = kv.x;
                KtPs[(c4+4*u+1)*64 + r] = kv.y;
                KtPs[(c4+4*u+2)*64 + r] = kv.z;
                KtPs[(c4+4*u+3)*64 + r] = kv.w;
                float4 vv = *(const float4*)(Vg + r*HD + c4 + 4*u);
                *(float4*)&Vs[r*64 + c4 + 4*u] = vv;
            }
        }
        __syncthreads();

        u64 s2[4][2];
#pragma unroll
        for (int i = 0; i < 4; i++) { s2[i][0] = 0ull; s2[i][1] = 0ull; }

#pragma unroll 8
        for (int dd = 0; dd < 64; dd++) {
            float4 a = *(const float4*)&Qt[dd*64 + r0];
            ulonglong2 b = *(const ulonglong2*)&KtPs[dd*64 + c0];
            float aa[4] = {a.x, a.y, a.z, a.w};
#pragma unroll
            for (int i = 0; i < 4; i++) {
                u64 a2 = dup2(aa[i]);
                ffma2(s2[i][0], a2, b.x);
                ffma2(s2[i][1], a2, b.y);
            }
        }
        __syncthreads();

#pragma unroll
        for (int i = 0; i < 4; i++) {
            float s0, s1, sA, sB;
            unpack2(s2[i][0], s0, s1);
            unpack2(s2[i][1], sA, sB);
            float rm = fmaxf(fmaxf(s0, s1), fmaxf(sA, sB)) * SCALEF;
#pragma unroll
            for (int off = 1; off < 16; off <<= 1)
                rm = fmaxf(rm, __shfl_xor_sync(0xffffffffu, rm, off));
            float mnew = fmaxf(mrow[i], rm);
            float alpha = __expf(mrow[i] - mnew);
            mrow[i] = mnew;
            float4 p4;
            p4.x = __expf(s0*SCALEF - mnew);
            p4.y = __expf(s1*SCALEF - mnew);
            p4.z = __expf(sA*SCALEF - mnew);
            p4.w = __expf(sB*SCALEF - mnew);
            *(float4*)&KtPs[(r0+i)*64 + c0] = p4;
            float rs = (p4.x + p4.y) + (p4.z + p4.w);
#pragma unroll
            for (int off = 1; off < 16; off <<= 1)
                rs += __shfl_xor_sync(0xffffffffu, rs, off);
            lrow[i] = lrow[i]*alpha + rs;
            u64 al = dup2(alpha);
            fmul2(o2[i][0], al);
            fmul2(o2[i][1], al);
        }
        __syncthreads();

#pragma unroll 4
        for (int j0 = 0; j0 < 64; j0 += 4) {
            float prow[4][4];
#pragma unroll
            for (int i = 0; i < 4; i++)
                *(float4*)prow[i] = *(const float4*)&KtPs[(r0+i)*64 + j0];
#pragma unroll
            for (int jj = 0; jj < 4; jj++) {
                ulonglong2 v = *(const ulonglong2*)&Vs[(j0+jj)*64 + c0];
#pragma unroll
                for (int i = 0; i < 4; i++) {
                    u64 pd = dup2(prow[i][jj]);
                    ffma2(o2[i][0], pd, v.x);
                    ffma2(o2[i][1], pd, v.y);
                }
            }
        }
    }

    const int b = bh / HEADS;
    const int head = bh - b * HEADS;
#pragma unroll
    for (int i = 0; i < 4; i++) {
        int n = q0 + r0 + i;
        u64 iv = dup2(1.0f / lrow[i]);
        fmul2(o2[i][0], iv);
        fmul2(o2[i][1], iv);
        ulonglong2 st; st.x = o2[i][0]; st.y = o2[i][1];
        *(ulonglong2*)&g_att[((size_t)(b*SEQ + n))*BDIM + head*HD + c0] = st;
    }
}

// ---------------------------------------------------------------------------
// GEMM 2: out = att @ proj_w^T + proj_b   (VERIFIED round-4 f32x2 version)
// Reads g_att internally.
// ---------------------------------------------------------------------------
__global__ __launch_bounds__(256)
void proj_gemm_kernel(const float* __restrict__ w, const float* __restrict__ bias,
                      float* __restrict__ out)
{
    __shared__ float As[8][132];
    __shared__ float Bs[8][132];

    const int tid = threadIdx.x;
    const int m0 = blockIdx.y * 128;
    const int f0 = blockIdx.x * 128;
    const int tx = tid & 15;
    const int ty = tid >> 4;

    const int lr = tid >> 1;
    const int lc = (tid & 1) * 4;
    const float* aptr = g_att + (size_t)(m0 + lr) * BDIM + lc;
    const float* bptr = w + (size_t)(f0 + lr) * BDIM + lc;

    u64 acc2[8][4];
#pragma unroll
    for (int i = 0; i < 8; i++)
#pragma unroll
        for (int jp = 0; jp < 4; jp++) acc2[i][jp] = 0ull;

    float4 av = *(const float4*)(aptr);
    float4 bv = *(const float4*)(bptr);

    for (int k0 = 0; k0 < BDIM; k0 += 8) {
        As[lc+0][lr] = av.x; As[lc+1][lr] = av.y; As[lc+2][lr] = av.z; As[lc+3][lr] = av.w;
        Bs[lc+0][lr] = bv.x; Bs[lc+1][lr] = bv.y; Bs[lc+2][lr] = bv.z; Bs[lc+3][lr] = bv.w;
        __syncthreads();
        if (k0 + 8 < BDIM) {
            av = *(const float4*)(aptr + k0 + 8);
            bv = *(const float4*)(bptr + k0 + 8);
        }
#pragma unroll
        for (int k = 0; k < 8; k++) {
            float a[8];
            *(float4*)(a)     = *(const float4*)&As[k][ty*8];
            *(float4*)(a + 4) = *(const float4*)&As[k][ty*8 + 4];
            ulonglong2 blo = *(const ulonglong2*)&Bs[k][tx*8];
            ulonglong2 bhi = *(const ulonglong2*)&Bs[k][tx*8 + 4];
            u64 b2[4] = {blo.x, blo.y, bhi.x, bhi.y};
#pragma unroll
            for (int i = 0; i < 8; i++) {
                u64 a2 = dup2(a[i]);
#pragma unroll
                for (int jp = 0; jp < 4; jp++) ffma2(acc2[i][jp], a2, b2[jp]);
            }
        }
        __syncthreads();
    }

    u64 bias2[4];
#pragma unroll
    for (int jp = 0; jp < 4; jp++)
        bias2[jp] = *(const u64*)&bias[f0 + tx*8 + 2*jp];

#pragma unroll
    for (int i = 0; i < 8; i++) {
        int m = m0 + ty*8 + i;
#pragma unroll
        for (int jp = 0; jp < 4; jp++) fadd2(acc2[i][jp], bias2[jp]);
        ulonglong2 lo; lo.x = acc2[i][0]; lo.y = acc2[i][1];
        ulonglong2 hi; hi.x = acc2[i][2]; hi.y = acc2[i][3];
        *(ulonglong2*)&out[(size_t)m * BDIM + f0 + tx*8]     = lo;
        *(ulonglong2*)&out[(size_t)m * BDIM + f0 + tx*8 + 4] = hi;
    }
}

// ---------------------------------------------------------------------------
extern "C" void kernel_launch(void* const* d_in, const int* in_sizes, int n_in,
                              void* d_out, int out_size)
{
    const float* x      = (const float*)d_in[0];
    // d_in[1] = H, d_in[2] = W (unused, fixed 48x48)
    const float* qkv_w  = (const float*)d_in[3];
    const float* proj_w = (const float*)d_in[4];
    const float* proj_b = (const float*)d_in[5];
    float* out = (float*)d_out;

    const int ATTN_SMEM = 3 * 64 * 64 * sizeof(float);  // 49152 B

    // GEMM 1 (tf32 mma.sync): qkv -> scatter Q/K/V
    dim3 g1(2304 / 128, MTOT / 128);   // 18 x 36
    qkv_mma_kernel<<<g1, 256>>>(x, qkv_w);

    // Flash attention (verified f32x2 SIMT)
    dim3 g2(SEQ / 64, BATCH * HEADS);  // 36 x 24
    attn_kernel<<<g2, 256, ATTN_SMEM>>>();

    // GEMM 2 (verified f32x2 SIMT): proj + bias
    dim3 g3(BDIM / 128, MTOT / 128);   // 6 x 36
    proj_gemm_kernel<<<g3, 256>>>(proj_w, proj_b, out);
}

// round 15
// speedup vs baseline: 2.0361x; 1.5894x over previous
#include <cuda_runtime.h>
#include <cstdint>
#include <math.h>

// Problem constants (fixed by the dataset)
#define BDIM   768
#define HEADS  12
#define HD     64
#define BATCH  2
#define SEQ    2304          // 48*48
#define MTOT   (BATCH*SEQ)   // 4608
#define SCALEF 0.125f        // 64^-0.5

typedef unsigned long long u64;

// ---- packed f32x2 helpers -------------------------------------------------
__device__ __forceinline__ u64 pack2(float x, float y) {
    u64 r; asm("mov.b64 %0,{%1,%2};" : "=l"(r) : "f"(x), "f"(y)); return r;
}
__device__ __forceinline__ u64 dup2(float x) { return pack2(x, x); }
__device__ __forceinline__ void ffma2(u64& d, u64 a, u64 b) {
    asm("fma.rn.f32x2 %0,%1,%2,%0;" : "+l"(d) : "l"(a), "l"(b));
}
__device__ __forceinline__ void fadd2(u64& d, u64 a) {
    asm("add.rn.f32x2 %0,%0,%1;" : "+l"(d) : "l"(a));
}

// ---- tf32 mma helpers (mapping VERIFIED by passing qkv kernel) ------------
__device__ __forceinline__ uint32_t to_tf32(float x) {
    uint32_t r; asm("cvt.rna.tf32.f32 %0, %1;" : "=r"(r) : "f"(x)); return r;
}
__device__ __forceinline__ void mma_tf32(float* c, const uint32_t* a,
                                         uint32_t b0, uint32_t b1) {
    asm volatile(
        "mma.sync.aligned.m16n8k8.row.col.f32.tf32.tf32.f32 "
        "{%0,%1,%2,%3}, {%4,%5,%6,%7}, {%8,%9}, {%0,%1,%2,%3};"
        : "+f"(c[0]), "+f"(c[1]), "+f"(c[2]), "+f"(c[3])
        : "r"(a[0]), "r"(a[1]), "r"(a[2]), "r"(a[3]), "r"(b0), "r"(b1));
}

// Scratch (device globals — allocation-free)
__device__ float g_Q[BATCH*HEADS*SEQ*HD];   // [B,h,N,d]
__device__ float g_K[BATCH*HEADS*SEQ*HD];
__device__ float g_V[BATCH*HEADS*SEQ*HD];
__device__ float g_att[MTOT*BDIM];          // [B,N,C]

// ===========================================================================
// qkv GEMM (tf32 mma.sync) — VERIFIED (round 12 pass).  Scatter into Q/K/V.
// ===========================================================================
__global__ __launch_bounds__(256)
void qkv_mma_kernel(const float* __restrict__ A, const float* __restrict__ W)
{
    __shared__ uint32_t As[2][128 * 20];
    __shared__ uint32_t Bs[2][128 * 20];

    const int tid  = threadIdx.x;
    const int lane = tid & 31;
    const int wid  = tid >> 5;
    const int quad = lane >> 2;
    const int tq   = lane & 3;
    const int wm   = wid >> 2;
    const int wn   = wid & 3;
    const int m0   = blockIdx.y * 128;
    const int f0   = blockIdx.x * 128;

    const int rowL = tid >> 1;
    const int cb   = (tid & 1) * 8;
    const float* Ap = A + (size_t)(m0 + rowL) * BDIM + cb;
    const float* Wp = W + (size_t)(f0 + rowL) * BDIM + cb;

    float acc[4][4][4];
#pragma unroll
    for (int mi = 0; mi < 4; mi++)
#pragma unroll
        for (int ni = 0; ni < 4; ni++)
#pragma unroll
            for (int r = 0; r < 4; r++) acc[mi][ni][r] = 0.f;

    float4 pa0 = *(const float4*)(Ap);
    float4 pa1 = *(const float4*)(Ap + 4);
    float4 pb0 = *(const float4*)(Wp);
    float4 pb1 = *(const float4*)(Wp + 4);

#define NCHUNK 48
    for (int c = 0; c < NCHUNK; c++) {
        const int buf = c & 1;
        {
            uint4 t0, t1;
            t0.x = to_tf32(pa0.x); t0.y = to_tf32(pa0.y);
            t0.z = to_tf32(pa0.z); t0.w = to_tf32(pa0.w);
            t1.x = to_tf32(pa1.x); t1.y = to_tf32(pa1.y);
            t1.z = to_tf32(pa1.z); t1.w = to_tf32(pa1.w);
            *(uint4*)&As[buf][rowL * 20 + cb]     = t0;
            *(uint4*)&As[buf][rowL * 20 + cb + 4] = t1;
            t0.x = to_tf32(pb0.x); t0.y = to_tf32(pb0.y);
            t0.z = to_tf32(pb0.z); t0.w = to_tf32(pb0.w);
            t1.x = to_tf32(pb1.x); t1.y = to_tf32(pb1.y);
            t1.z = to_tf32(pb1.z); t1.w = to_tf32(pb1.w);
            *(uint4*)&Bs[buf][rowL * 20 + cb]     = t0;
            *(uint4*)&Bs[buf][rowL * 20 + cb + 4] = t1;
        }
        __syncthreads();
        if (c + 1 < NCHUNK) {
            const int k0 = (c + 1) * 16;
            pa0 = *(const float4*)(Ap + k0);
            pa1 = *(const float4*)(Ap + k0 + 4);
            pb0 = *(const float4*)(Wp + k0);
            pb1 = *(const float4*)(Wp + k0 + 4);
        }
#pragma unroll
        for (int ks = 0; ks < 2; ks++) {
            uint32_t af[4][4];
#pragma unroll
            for (int mi = 0; mi < 4; mi++) {
                const int rr = wm * 64 + mi * 16 + quad;
                af[mi][0] = As[buf][rr * 20 + ks * 8 + tq];
                af[mi][1] = As[buf][(rr + 8) * 20 + ks * 8 + tq];
                af[mi][2] = As[buf][rr * 20 + ks * 8 + tq + 4];
                af[mi][3] = As[buf][(rr + 8) * 20 + ks * 8 + tq + 4];
            }
#pragma unroll
            for (int ni = 0; ni < 4; ni++) {
                const int cc = wn * 32 + ni * 8 + quad;
                uint32_t b0 = Bs[buf][cc * 20 + ks * 8 + tq];
                uint32_t b1 = Bs[buf][cc * 20 + ks * 8 + tq + 4];
#pragma unroll
                for (int mi = 0; mi < 4; mi++)
                    mma_tf32(acc[mi][ni], af[mi], b0, b1);
            }
        }
        __syncthreads();
    }

#pragma unroll
    for (int mi = 0; mi < 4; mi++) {
#pragma unroll
        for (int ni = 0; ni < 4; ni++) {
            const int m = m0 + wm * 64 + mi * 16 + quad;
            const int f = f0 + wn * 32 + ni * 8 + 2 * tq;
            const int t    = f / BDIM;
            const int rem  = f - t * BDIM;
            const int head = rem >> 6;
            const int dd   = rem & 63;
            float* dst = (t == 0) ? g_Q : ((t == 1) ? g_K : g_V);
#pragma unroll
            for (int h = 0; h < 2; h++) {
                const int mm = m + 8 * h;
                const int b  = mm / SEQ;
                const int n  = mm - b * SEQ;
                float2 v; v.x = acc[mi][ni][2*h]; v.y = acc[mi][ni][2*h+1];
                *(float2*)&dst[(((size_t)(b * HEADS + head)) * SEQ + n) * HD + dd] = v;
            }
        }
    }
}

// ===========================================================================
// proj GEMM (tf32 mma.sync, same verified mapping): out = att@proj_w^T + b
// ===========================================================================
__global__ __launch_bounds__(256)
void proj_mma_kernel(const float* __restrict__ W, const float* __restrict__ bias,
                     float* __restrict__ out)
{
    __shared__ uint32_t As[2][128 * 20];
    __shared__ uint32_t Bs[2][128 * 20];

    const int tid  = threadIdx.x;
    const int lane = tid & 31;
    const int wid  = tid >> 5;
    const int quad = lane >> 2;
    const int tq   = lane & 3;
    const int wm   = wid >> 2;
    const int wn   = wid & 3;
    const int m0   = blockIdx.y * 128;
    const int f0   = blockIdx.x * 128;

    const int rowL = tid >> 1;
    const int cb   = (tid & 1) * 8;
    const float* Ap = g_att + (size_t)(m0 + rowL) * BDIM + cb;
    const float* Wp = W + (size_t)(f0 + rowL) * BDIM + cb;

    float acc[4][4][4];
#pragma unroll
    for (int mi = 0; mi < 4; mi++)
#pragma unroll
        for (int ni = 0; ni < 4; ni++)
#pragma unroll
            for (int r = 0; r < 4; r++) acc[mi][ni][r] = 0.f;

    float4 pa0 = *(const float4*)(Ap);
    float4 pa1 = *(const float4*)(Ap + 4);
    float4 pb0 = *(const float4*)(Wp);
    float4 pb1 = *(const float4*)(Wp + 4);

    for (int c = 0; c < NCHUNK; c++) {
        const int buf = c & 1;
        {
            uint4 t0, t1;
            t0.x = to_tf32(pa0.x); t0.y = to_tf32(pa0.y);
            t0.z = to_tf32(pa0.z); t0.w = to_tf32(pa0.w);
            t1.x = to_tf32(pa1.x); t1.y = to_tf32(pa1.y);
            t1.z = to_tf32(pa1.z); t1.w = to_tf32(pa1.w);
            *(uint4*)&As[buf][rowL * 20 + cb]     = t0;
            *(uint4*)&As[buf][rowL * 20 + cb + 4] = t1;
            t0.x = to_tf32(pb0.x); t0.y = to_tf32(pb0.y);
            t0.z = to_tf32(pb0.z); t0.w = to_tf32(pb0.w);
            t1.x = to_tf32(pb1.x); t1.y = to_tf32(pb1.y);
            t1.z = to_tf32(pb1.z); t1.w = to_tf32(pb1.w);
            *(uint4*)&Bs[buf][rowL * 20 + cb]     = t0;
            *(uint4*)&Bs[buf][rowL * 20 + cb + 4] = t1;
        }
        __syncthreads();
        if (c + 1 < NCHUNK) {
            const int k0 = (c + 1) * 16;
            pa0 = *(const float4*)(Ap + k0);
            pa1 = *(const float4*)(Ap + k0 + 4);
            pb0 = *(const float4*)(Wp + k0);
            pb1 = *(const float4*)(Wp + k0 + 4);
        }
#pragma unroll
        for (int ks = 0; ks < 2; ks++) {
            uint32_t af[4][4];
#pragma unroll
            for (int mi = 0; mi < 4; mi++) {
                const int rr = wm * 64 + mi * 16 + quad;
                af[mi][0] = As[buf][rr * 20 + ks * 8 + tq];
                af[mi][1] = As[buf][(rr + 8) * 20 + ks * 8 + tq];
                af[mi][2] = As[buf][rr * 20 + ks * 8 + tq + 4];
                af[mi][3] = As[buf][(rr + 8) * 20 + ks * 8 + tq + 4];
            }
#pragma unroll
            for (int ni = 0; ni < 4; ni++) {
                const int cc = wn * 32 + ni * 8 + quad;
                uint32_t b0 = Bs[buf][cc * 20 + ks * 8 + tq];
                uint32_t b1 = Bs[buf][cc * 20 + ks * 8 + tq + 4];
#pragma unroll
                for (int mi = 0; mi < 4; mi++)
                    mma_tf32(acc[mi][ni], af[mi], b0, b1);
            }
        }
        __syncthreads();
    }

#pragma unroll
    for (int mi = 0; mi < 4; mi++) {
#pragma unroll
        for (int ni = 0; ni < 4; ni++) {
            const int m = m0 + wm * 64 + mi * 16 + quad;
            const int f = f0 + wn * 32 + ni * 8 + 2 * tq;
            float2 bv = *(const float2*)&bias[f];
#pragma unroll
            for (int h = 0; h < 2; h++) {
                const int mm = m + 8 * h;
                float2 v;
                v.x = acc[mi][ni][2*h]     + bv.x;
                v.y = acc[mi][ni][2*h + 1] + bv.y;
                *(float2*)&out[(size_t)mm * BDIM + f] = v;
            }
        }
    }
}

// ===========================================================================
// Flash attention, tf32 mma.sync.  Per (b,h): Br=Bc=64.  128 threads, 4 warps;
// each warp owns 16 q-rows (rows wid*16+quad, +8) x all 64 cols.
// Smem buffers are SEPARATE (P does NOT alias K):
//   QP[64][68] : Q staging (read once into regs) -> P tile per iteration
//   Ks[64][68] : K tile
//   Vs[64][72] : V tile
// Dynamic smem 53248 B.  Full __syncthreads() discipline.
// ===========================================================================
#define AT_QP 0
#define AT_KS (64*68)
#define AT_VS (64*68*2)
#define AT_WORDS (64*68*2 + 64*72)     // 13312 words = 53248 B

__global__ __launch_bounds__(128)
void attn_mma_kernel()
{
    extern __shared__ uint32_t smw[];
    uint32_t* QP = smw + AT_QP;
    uint32_t* Ks = smw + AT_KS;
    uint32_t* Vs = smw + AT_VS;

    const int tid  = threadIdx.x;
    const int lane = tid & 31;
    const int wid  = tid >> 5;        // 0..3
    const int quad = lane >> 2;       // 0..7
    const int tq   = lane & 3;        // 0..3
    const int bh   = blockIdx.y;
    const int q0   = blockIdx.x * 64;
    const int b    = bh / HEADS;
    const int head = bh - b * HEADS;

    const int rowL = tid >> 1;            // 0..63
    const int cbL  = (tid & 1) * 32;      // 0 or 32

    // ---- stage Q (tf32) into QP ------------------------------------------
    {
        const float* Qg = g_Q + ((size_t)bh * SEQ + q0) * HD;
#pragma unroll
        for (int u = 0; u < 8; u++) {
            float4 v = *(const float4*)(Qg + (size_t)rowL * HD + cbL + 4 * u);
            uint4 t;
            t.x = to_tf32(v.x); t.y = to_tf32(v.y);
            t.z = to_tf32(v.z); t.w = to_tf32(v.w);
            *(uint4*)&QP[rowL * 68 + cbL + 4 * u] = t;
        }
    }
    __syncthreads();

    // ---- extract Q fragments (held in registers for entire kernel) --------
    const int arow = wid * 16 + quad;
    uint32_t qf[8][4];
#pragma unroll
    for (int ks = 0; ks < 8; ks++) {
        qf[ks][0] = QP[arow * 68 + ks * 8 + tq];
        qf[ks][1] = QP[(arow + 8) * 68 + ks * 8 + tq];
        qf[ks][2] = QP[arow * 68 + ks * 8 + tq + 4];
        qf[ks][3] = QP[(arow + 8) * 68 + ks * 8 + tq + 4];
    }

    float o[8][4];
#pragma unroll
    for (int ni = 0; ni < 8; ni++)
#pragma unroll
        for (int r = 0; r < 4; r++) o[ni][r] = 0.f;
    float mr0 = -1e30f, mr1 = -1e30f, l0 = 0.f, l1 = 0.f;

    const float* Kg = g_K + (size_t)bh * SEQ * HD;
    const float* Vg = g_V + (size_t)bh * SEQ * HD;

    for (int kt = 0; kt < SEQ; kt += 64) {
        // prev iteration's PV reads of QP(P)/Vs done; Q extraction done (iter 0)
        __syncthreads();
        // ---- load K and V tiles (tf32) ------------------------------------
#pragma unroll
        for (int u = 0; u < 8; u++) {
            float4 kv = *(const float4*)(Kg + (size_t)(kt + rowL) * HD + cbL + 4 * u);
            uint4 t;
            t.x = to_tf32(kv.x); t.y = to_tf32(kv.y);
            t.z = to_tf32(kv.z); t.w = to_tf32(kv.w);
            *(uint4*)&Ks[rowL * 68 + cbL + 4 * u] = t;
            float4 vv = *(const float4*)(Vg + (size_t)(kt + rowL) * HD + cbL + 4 * u);
            t.x = to_tf32(vv.x); t.y = to_tf32(vv.y);
            t.z = to_tf32(vv.z); t.w = to_tf32(vv.w);
            *(uint4*)&Vs[rowL * 72 + cbL + 4 * u] = t;
        }
        __syncthreads();

        // ---- S = Q K^T -----------------------------------------------------
        float s[8][4];
#pragma unroll
        for (int ni = 0; ni < 8; ni++)
#pragma unroll
            for (int r = 0; r < 4; r++) s[ni][r] = 0.f;
#pragma unroll
        for (int ks = 0; ks < 8; ks++) {
#pragma unroll
            for (int ni = 0; ni < 8; ni++) {
                const int cc = ni * 8 + quad;
                uint32_t b0 = Ks[cc * 68 + ks * 8 + tq];
                uint32_t b1 = Ks[cc * 68 + ks * 8 + tq + 4];
                mma_tf32(s[ni], qf[ks], b0, b1);
            }
        }

        // ---- online softmax; write P (tf32) into QP ------------------------
        // row 0 of this thread = arow : s[ni][0], s[ni][1]
        {
            float rm = -1e30f;
#pragma unroll
            for (int ni = 0; ni < 8; ni++)
                rm = fmaxf(rm, fmaxf(s[ni][0], s[ni][1]));
            rm *= SCALEF;
            rm = fmaxf(rm, __shfl_xor_sync(0xffffffffu, rm, 1));
            rm = fmaxf(rm, __shfl_xor_sync(0xffffffffu, rm, 2));
            float mnew = fmaxf(mr0, rm);
            float alpha = __expf(mr0 - mnew);
            mr0 = mnew;
            float rs = 0.f;
#pragma unroll
            for (int ni = 0; ni < 8; ni++) {
                float p0 = __expf(s[ni][0] * SCALEF - mnew);
                float p1 = __expf(s[ni][1] * SCALEF - mnew);
                rs += p0 + p1;
                uint2 pp; pp.x = to_tf32(p0); pp.y = to_tf32(p1);
                *(uint2*)&QP[arow * 68 + ni * 8 + 2 * tq] = pp;
                o[ni][0] *= alpha; o[ni][1] *= alpha;
            }
            rs += __shfl_xor_sync(0xffffffffu, rs, 1);
            rs += __shfl_xor_sync(0xffffffffu, rs, 2);
            l0 = l0 * alpha + rs;
        }
        // row 1 = arow + 8 : s[ni][2], s[ni][3]
        {
            float rm = -1e30f;
#pragma unroll
            for (int ni = 0; ni < 8; ni++)
                rm = fmaxf(rm, fmaxf(s[ni][2], s[ni][3]));
            rm *= SCALEF;
            rm = fmaxf(rm, __shfl_xor_sync(0xffffffffu, rm, 1));
            rm = fmaxf(rm, __shfl_xor_sync(0xffffffffu, rm, 2));
            float mnew = fmaxf(mr1, rm);
            float alpha = __expf(mr1 - mnew);
            mr1 = mnew;
            float rs = 0.f;
#pragma unroll
            for (int ni = 0; ni < 8; ni++) {
                float p0 = __expf(s[ni][2] * SCALEF - mnew);
                float p1 = __expf(s[ni][3] * SCALEF - mnew);
                rs += p0 + p1;
                uint2 pp; pp.x = to_tf32(p0); pp.y = to_tf32(p1);
                *(uint2*)&QP[(arow + 8) * 68 + ni * 8 + 2 * tq] = pp;
                o[ni][2] *= alpha; o[ni][3] *= alpha;
            }
            rs += __shfl_xor_sync(0xffffffffu, rs, 1);
            rs += __shfl_xor_sync(0xffffffffu, rs, 2);
            l1 = l1 * alpha + rs;
        }
        __syncthreads();   // all P writes visible before PV fragment loads

        // ---- O += P @ V ----------------------------------------------------
#pragma unroll
        for (int ks = 0; ks < 8; ks++) {
            uint32_t pa[4];
            pa[0] = QP[arow * 68 + ks * 8 + tq];
            pa[1] = QP[(arow + 8) * 68 + ks * 8 + tq];
            pa[2] = QP[arow * 68 + ks * 8 + tq + 4];
            pa[3] = QP[(arow + 8) * 68 + ks * 8 + tq + 4];
#pragma unroll
            for (int ni = 0; ni < 8; ni++) {
                uint32_t b0 = Vs[(ks * 8 + tq) * 72 + ni * 8 + quad];
                uint32_t b1 = Vs[(ks * 8 + tq + 4) * 72 + ni * 8 + quad];
                mma_tf32(o[ni], pa, b0, b1);
            }
        }
    }

    // ---- epilogue ---------------------------------------------------------
    const float inv0 = 1.0f / l0;
    const float inv1 = 1.0f / l1;
    const size_t base0 = ((size_t)(b * SEQ + q0 + arow)) * BDIM + head * HD;
    const size_t base1 = ((size_t)(b * SEQ + q0 + arow + 8)) * BDIM + head * HD;
#pragma unroll
    for (int ni = 0; ni < 8; ni++) {
        const int dd = ni * 8 + 2 * tq;
        float2 v0; v0.x = o[ni][0] * inv0; v0.y = o[ni][1] * inv0;
        float2 v1; v1.x = o[ni][2] * inv1; v1.y = o[ni][3] * inv1;
        *(float2*)&g_att[base0 + dd] = v0;
        *(float2*)&g_att[base1 + dd] = v1;
    }
}

// ---------------------------------------------------------------------------
extern "C" void kernel_launch(void* const* d_in, const int* in_sizes, int n_in,
                              void* d_out, int out_size)
{
    const float* x      = (const float*)d_in[0];
    // d_in[1] = H, d_in[2] = W (unused, fixed 48x48)
    const float* qkv_w  = (const float*)d_in[3];
    const float* proj_w = (const float*)d_in[4];
    const float* proj_b = (const float*)d_in[5];
    float* out = (float*)d_out;

    const int ATTN_SMEM = AT_WORDS * 4;   // 53248 B
    cudaFuncSetAttribute(attn_mma_kernel,
                         cudaFuncAttributeMaxDynamicSharedMemorySize, ATTN_SMEM);

    // GEMM 1 (verified tf32 mma): qkv -> scatter Q/K/V
    dim3 g1(2304 / 128, MTOT / 128);   // 18 x 36
    qkv_mma_kernel<<<g1, 256>>>(x, qkv_w);

    // Flash attention (tf32 mma, separate P buffer, full syncs)
    dim3 g2(SEQ / 64, BATCH * HEADS);  // 36 x 24
    attn_mma_kernel<<<g2, 128, ATTN_SMEM>>>();

    // GEMM 2 (tf32 mma, verified mapping): proj + bias
    dim3 g3(BDIM / 128, MTOT / 128);   // 6 x 36
    proj_mma_kernel<<<g3, 256>>>(proj_w, proj_b, out);
}

// round 17
// speedup vs baseline: 2.8855x; 1.4172x over previous
#include <cuda_runtime.h>
#include <cstdint>
#include <math.h>

// Problem constants (fixed by the dataset)
#define BDIM   768
#define HEADS  12
#define HD     64
#define BATCH  2
#define SEQ    2304          // 48*48
#define MTOT   (BATCH*SEQ)   // 4608
#define SCALEF 0.125f        // 64^-0.5 (power of two: exact when folded into Q)

// ---- tf32 mma helpers (mapping VERIFIED) ----------------------------------
__device__ __forceinline__ uint32_t to_tf32(float x) {
    uint32_t r; asm("cvt.rna.tf32.f32 %0, %1;" : "=r"(r) : "f"(x)); return r;
}
__device__ __forceinline__ void mma_tf32(float* c, const uint32_t* a,
                                         uint32_t b0, uint32_t b1) {
    asm volatile(
        "mma.sync.aligned.m16n8k8.row.col.f32.tf32.tf32.f32 "
        "{%0,%1,%2,%3}, {%4,%5,%6,%7}, {%8,%9}, {%0,%1,%2,%3};"
        : "+f"(c[0]), "+f"(c[1]), "+f"(c[2]), "+f"(c[3])
        : "r"(a[0]), "r"(a[1]), "r"(a[2]), "r"(a[3]), "r"(b0), "r"(b1));
}

// Scratch (device globals — allocation-free)
__device__ float g_Q[BATCH*HEADS*SEQ*HD];   // [B,h,N,d]
__device__ float g_K[BATCH*HEADS*SEQ*HD];
__device__ float g_V[BATCH*HEADS*SEQ*HD];
__device__ float g_att[MTOT*BDIM];          // [B,N,C]

// ===========================================================================
// qkv GEMM (tf32 mma.sync) — VERIFIED.  Scatter into Q/K/V.
// ===========================================================================
__global__ __launch_bounds__(256)
void qkv_mma_kernel(const float* __restrict__ A, const float* __restrict__ W)
{
    __shared__ uint32_t As[2][128 * 20];
    __shared__ uint32_t Bs[2][128 * 20];

    const int tid  = threadIdx.x;
    const int lane = tid & 31;
    const int wid  = tid >> 5;
    const int quad = lane >> 2;
    const int tq   = lane & 3;
    const int wm   = wid >> 2;
    const int wn   = wid & 3;
    const int m0   = blockIdx.y * 128;
    const int f0   = blockIdx.x * 128;

    const int rowL = tid >> 1;
    const int cb   = (tid & 1) * 8;
    const float* Ap = A + (size_t)(m0 + rowL) * BDIM + cb;
    const float* Wp = W + (size_t)(f0 + rowL) * BDIM + cb;

    float acc[4][4][4];
#pragma unroll
    for (int mi = 0; mi < 4; mi++)
#pragma unroll
        for (int ni = 0; ni < 4; ni++)
#pragma unroll
            for (int r = 0; r < 4; r++) acc[mi][ni][r] = 0.f;

    float4 pa0 = *(const float4*)(Ap);
    float4 pa1 = *(const float4*)(Ap + 4);
    float4 pb0 = *(const float4*)(Wp);
    float4 pb1 = *(const float4*)(Wp + 4);

#define NCHUNK 48
    for (int c = 0; c < NCHUNK; c++) {
        const int buf = c & 1;
        {
            uint4 t0, t1;
            t0.x = to_tf32(pa0.x); t0.y = to_tf32(pa0.y);
            t0.z = to_tf32(pa0.z); t0.w = to_tf32(pa0.w);
            t1.x = to_tf32(pa1.x); t1.y = to_tf32(pa1.y);
            t1.z = to_tf32(pa1.z); t1.w = to_tf32(pa1.w);
            *(uint4*)&As[buf][rowL * 20 + cb]     = t0;
            *(uint4*)&As[buf][rowL * 20 + cb + 4] = t1;
            t0.x = to_tf32(pb0.x); t0.y = to_tf32(pb0.y);
            t0.z = to_tf32(pb0.z); t0.w = to_tf32(pb0.w);
            t1.x = to_tf32(pb1.x); t1.y = to_tf32(pb1.y);
            t1.z = to_tf32(pb1.z); t1.w = to_tf32(pb1.w);
            *(uint4*)&Bs[buf][rowL * 20 + cb]     = t0;
            *(uint4*)&Bs[buf][rowL * 20 + cb + 4] = t1;
        }
        __syncthreads();
        if (c + 1 < NCHUNK) {
            const int k0 = (c + 1) * 16;
            pa0 = *(const float4*)(Ap + k0);
            pa1 = *(const float4*)(Ap + k0 + 4);
            pb0 = *(const float4*)(Wp + k0);
            pb1 = *(const float4*)(Wp + k0 + 4);
        }
#pragma unroll
        for (int ks = 0; ks < 2; ks++) {
            uint32_t af[4][4];
#pragma unroll
            for (int mi = 0; mi < 4; mi++) {
                const int rr = wm * 64 + mi * 16 + quad;
                af[mi][0] = As[buf][rr * 20 + ks * 8 + tq];
                af[mi][1] = As[buf][(rr + 8) * 20 + ks * 8 + tq];
                af[mi][2] = As[buf][rr * 20 + ks * 8 + tq + 4];
                af[mi][3] = As[buf][(rr + 8) * 20 + ks * 8 + tq + 4];
            }
#pragma unroll
            for (int ni = 0; ni < 4; ni++) {
                const int cc = wn * 32 + ni * 8 + quad;
                uint32_t b0 = Bs[buf][cc * 20 + ks * 8 + tq];
                uint32_t b1 = Bs[buf][cc * 20 + ks * 8 + tq + 4];
#pragma unroll
                for (int mi = 0; mi < 4; mi++)
                    mma_tf32(acc[mi][ni], af[mi], b0, b1);
            }
        }
        __syncthreads();
    }

#pragma unroll
    for (int mi = 0; mi < 4; mi++) {
#pragma unroll
        for (int ni = 0; ni < 4; ni++) {
            const int m = m0 + wm * 64 + mi * 16 + quad;
            const int f = f0 + wn * 32 + ni * 8 + 2 * tq;
            const int t    = f / BDIM;
            const int rem  = f - t * BDIM;
            const int head = rem >> 6;
            const int dd   = rem & 63;
            float* dst = (t == 0) ? g_Q : ((t == 1) ? g_K : g_V);
#pragma unroll
            for (int h = 0; h < 2; h++) {
                const int mm = m + 8 * h;
                const int b  = mm / SEQ;
                const int n  = mm - b * SEQ;
                float2 v; v.x = acc[mi][ni][2*h]; v.y = acc[mi][ni][2*h+1];
                *(float2*)&dst[(((size_t)(b * HEADS + head)) * SEQ + n) * HD + dd] = v;
            }
        }
    }
}

// ===========================================================================
// proj GEMM (tf32 mma.sync, verified mapping): out = att@proj_w^T + bias
// ===========================================================================
__global__ __launch_bounds__(256)
void proj_mma_kernel(const float* __restrict__ W, const float* __restrict__ bias,
                     float* __restrict__ out)
{
    __shared__ uint32_t As[2][128 * 20];
    __shared__ uint32_t Bs[2][128 * 20];

    const int tid  = threadIdx.x;
    const int lane = tid & 31;
    const int wid  = tid >> 5;
    const int quad = lane >> 2;
    const int tq   = lane & 3;
    const int wm   = wid >> 2;
    const int wn   = wid & 3;
    const int m0   = blockIdx.y * 128;
    const int f0   = blockIdx.x * 128;

    const int rowL = tid >> 1;
    const int cb   = (tid & 1) * 8;
    const float* Ap = g_att + (size_t)(m0 + rowL) * BDIM + cb;
    const float* Wp = W + (size_t)(f0 + rowL) * BDIM + cb;

    float acc[4][4][4];
#pragma unroll
    for (int mi = 0; mi < 4; mi++)
#pragma unroll
        for (int ni = 0; ni < 4; ni++)
#pragma unroll
            for (int r = 0; r < 4; r++) acc[mi][ni][r] = 0.f;

    float4 pa0 = *(const float4*)(Ap);
    float4 pa1 = *(const float4*)(Ap + 4);
    float4 pb0 = *(const float4*)(Wp);
    float4 pb1 = *(const float4*)(Wp + 4);

    for (int c = 0; c < NCHUNK; c++) {
        const int buf = c & 1;
        {
            uint4 t0, t1;
            t0.x = to_tf32(pa0.x); t0.y = to_tf32(pa0.y);
            t0.z = to_tf32(pa0.z); t0.w = to_tf32(pa0.w);
            t1.x = to_tf32(pa1.x); t1.y = to_tf32(pa1.y);
            t1.z = to_tf32(pa1.z); t1.w = to_tf32(pa1.w);
            *(uint4*)&As[buf][rowL * 20 + cb]     = t0;
            *(uint4*)&As[buf][rowL * 20 + cb + 4] = t1;
            t0.x = to_tf32(pb0.x); t0.y = to_tf32(pb0.y);
            t0.z = to_tf32(pb0.z); t0.w = to_tf32(pb0.w);
            t1.x = to_tf32(pb1.x); t1.y = to_tf32(pb1.y);
            t1.z = to_tf32(pb1.z); t1.w = to_tf32(pb1.w);
            *(uint4*)&Bs[buf][rowL * 20 + cb]     = t0;
            *(uint4*)&Bs[buf][rowL * 20 + cb + 4] = t1;
        }
        __syncthreads();
        if (c + 1 < NCHUNK) {
            const int k0 = (c + 1) * 16;
            pa0 = *(const float4*)(Ap + k0);
            pa1 = *(const float4*)(Ap + k0 + 4);
            pb0 = *(const float4*)(Wp + k0);
            pb1 = *(const float4*)(Wp + k0 + 4);
        }
#pragma unroll
        for (int ks = 0; ks < 2; ks++) {
            uint32_t af[4][4];
#pragma unroll
            for (int mi = 0; mi < 4; mi++) {
                const int rr = wm * 64 + mi * 16 + quad;
                af[mi][0] = As[buf][rr * 20 + ks * 8 + tq];
                af[mi][1] = As[buf][(rr + 8) * 20 + ks * 8 + tq];
                af[mi][2] = As[buf][rr * 20 + ks * 8 + tq + 4];
                af[mi][3] = As[buf][(rr + 8) * 20 + ks * 8 + tq + 4];
            }
#pragma unroll
            for (int ni = 0; ni < 4; ni++) {
                const int cc = wn * 32 + ni * 8 + quad;
                uint32_t b0 = Bs[buf][cc * 20 + ks * 8 + tq];
                uint32_t b1 = Bs[buf][cc * 20 + ks * 8 + tq + 4];
#pragma unroll
                for (int mi = 0; mi < 4; mi++)
                    mma_tf32(acc[mi][ni], af[mi], b0, b1);
            }
        }
        __syncthreads();
    }

#pragma unroll
    for (int mi = 0; mi < 4; mi++) {
#pragma unroll
        for (int ni = 0; ni < 4; ni++) {
            const int m = m0 + wm * 64 + mi * 16 + quad;
            const int f = f0 + wn * 32 + ni * 8 + 2 * tq;
            float2 bv = *(const float2*)&bias[f];
#pragma unroll
            for (int h = 0; h < 2; h++) {
                const int mm = m + 8 * h;
                float2 v;
                v.x = acc[mi][ni][2*h]     + bv.x;
                v.y = acc[mi][ni][2*h + 1] + bv.y;
                *(float2*)&out[(size_t)mm * BDIM + f] = v;
            }
        }
    }
}

// ===========================================================================
// Flash attention, tf32 mma.sync, Q-tile = 128 rows, 256 threads (8 warps).
// Warp w owns q-rows w*16 .. w*16+15 (same verified per-warp math as before).
// Smem (separate buffers, no aliasing):
//   QP[128][68] : Q staging (scaled by 0.125, read once to regs) -> P tile
//   Ks[64][68]  : K tile
//   Vs[64][72]  : V tile
// Dynamic smem 70656 B.  Block syncs around shared K/V; warp sync for P.
// ===========================================================================
#define AT_QP 0
#define AT_KS (128*68)
#define AT_VS (128*68 + 64*68)
#define AT_WORDS (128*68 + 64*68 + 64*72)   // 17664 words = 70656 B

__global__ __launch_bounds__(256)
void attn_mma_kernel()
{
    extern __shared__ uint32_t smw[];
    uint32_t* QP = smw + AT_QP;
    uint32_t* Ks = smw + AT_KS;
    uint32_t* Vs = smw + AT_VS;

    const int tid  = threadIdx.x;
    const int lane = tid & 31;
    const int wid  = tid >> 5;        // 0..7
    const int quad = lane >> 2;       // 0..7
    const int tq   = lane & 3;        // 0..3
    const int bh   = blockIdx.y;
    const int q0   = blockIdx.x * 128;
    const int b    = bh / HEADS;
    const int head = bh - b * HEADS;

    // ---- stage Q (pre-scaled by SCALEF, exact) into QP --------------------
    {
        const float* Qg = g_Q + ((size_t)bh * SEQ + q0) * HD;
        const int rowQ = tid >> 1;            // 0..127
        const int cbQ  = (tid & 1) * 32;      // 0 or 32
#pragma unroll
        for (int u = 0; u < 8; u++) {
            float4 v = *(const float4*)(Qg + (size_t)rowQ * HD + cbQ + 4 * u);
            uint4 t;
            t.x = to_tf32(v.x * SCALEF); t.y = to_tf32(v.y * SCALEF);
            t.z = to_tf32(v.z * SCALEF); t.w = to_tf32(v.w * SCALEF);
            *(uint4*)&QP[rowQ * 68 + cbQ + 4 * u] = t;
        }
    }
    __syncthreads();

    // ---- extract Q fragments (registers for entire kernel) ----------------
    const int arow = wid * 16 + quad;         // 0..127
    uint32_t qf[8][4];
#pragma unroll
    for (int ks = 0; ks < 8; ks++) {
        qf[ks][0] = QP[arow * 68 + ks * 8 + tq];
        qf[ks][1] = QP[(arow + 8) * 68 + ks * 8 + tq];
        qf[ks][2] = QP[arow * 68 + ks * 8 + tq + 4];
        qf[ks][3] = QP[(arow + 8) * 68 + ks * 8 + tq + 4];
    }

    float o[8][4];
#pragma unroll
    for (int ni = 0; ni < 8; ni++)
#pragma unroll
        for (int r = 0; r < 4; r++) o[ni][r] = 0.f;
    float mr0 = -1e30f, mr1 = -1e30f, l0 = 0.f, l1 = 0.f;

    const float* Kg = g_K + (size_t)bh * SEQ * HD;
    const float* Vg = g_V + (size_t)bh * SEQ * HD;
    const int rowK = tid >> 2;            // 0..63
    const int cbK  = (tid & 3) * 16;      // 0,16,32,48

    for (int kt = 0; kt < SEQ; kt += 64) {
        // prev iter's S reads of Ks and PV reads of Vs done; Q extraction done
        __syncthreads();
        // ---- load K and V tiles (tf32), 256 threads -----------------------
#pragma unroll
        for (int u = 0; u < 4; u++) {
            float4 kv = *(const float4*)(Kg + (size_t)(kt + rowK) * HD + cbK + 4 * u);
            uint4 t;
            t.x = to_tf32(kv.x); t.y = to_tf32(kv.y);
            t.z = to_tf32(kv.z); t.w = to_tf32(kv.w);
            *(uint4*)&Ks[rowK * 68 + cbK + 4 * u] = t;
            float4 vv = *(const float4*)(Vg + (size_t)(kt + rowK) * HD + cbK + 4 * u);
            t.x = to_tf32(vv.x); t.y = to_tf32(vv.y);
            t.z = to_tf32(vv.z); t.w = to_tf32(vv.w);
            *(uint4*)&Vs[rowK * 72 + cbK + 4 * u] = t;
        }
        __syncthreads();

        // ---- S = (Q*scale) K^T --------------------------------------------
        float s[8][4];
#pragma unroll
        for (int ni = 0; ni < 8; ni++)
#pragma unroll
            for (int r = 0; r < 4; r++) s[ni][r] = 0.f;
#pragma unroll
        for (int ks = 0; ks < 8; ks++) {
#pragma unroll
            for (int ni = 0; ni < 8; ni++) {
                const int cc = ni * 8 + quad;
                uint32_t b0 = Ks[cc * 68 + ks * 8 + tq];
                uint32_t b1 = Ks[cc * 68 + ks * 8 + tq + 4];
                mma_tf32(s[ni], qf[ks], b0, b1);
            }
        }

        // ---- online softmax; write P (tf32) into QP (own warp rows) -------
        {
            float rm = -1e30f;
#pragma unroll
            for (int ni = 0; ni < 8; ni++)
                rm = fmaxf(rm, fmaxf(s[ni][0], s[ni][1]));
            rm = fmaxf(rm, __shfl_xor_sync(0xffffffffu, rm, 1));
            rm = fmaxf(rm, __shfl_xor_sync(0xffffffffu, rm, 2));
            float mnew = fmaxf(mr0, rm);
            float alpha = __expf(mr0 - mnew);
            mr0 = mnew;
            float rs = 0.f;
#pragma unroll
            for (int ni = 0; ni < 8; ni++) {
                float p0 = __expf(s[ni][0] - mnew);
                float p1 = __expf(s[ni][1] - mnew);
                rs += p0 + p1;
                uint2 pp; pp.x = to_tf32(p0); pp.y = to_tf32(p1);
                *(uint2*)&QP[arow * 68 + ni * 8 + 2 * tq] = pp;
                o[ni][0] *= alpha; o[ni][1] *= alpha;
            }
            rs += __shfl_xor_sync(0xffffffffu, rs, 1);
            rs += __shfl_xor_sync(0xffffffffu, rs, 2);
            l0 = l0 * alpha + rs;
        }
        {
            float rm = -1e30f;
#pragma unroll
            for (int ni = 0; ni < 8; ni++)
                rm = fmaxf(rm, fmaxf(s[ni][2], s[ni][3]));
            rm = fmaxf(rm, __shfl_xor_sync(0xffffffffu, rm, 1));
            rm = fmaxf(rm, __shfl_xor_sync(0xffffffffu, rm, 2));
            float mnew = fmaxf(mr1, rm);
            float alpha = __expf(mr1 - mnew);
            mr1 = mnew;
            float rs = 0.f;
#pragma unroll
            for (int ni = 0; ni < 8; ni++) {
                float p0 = __expf(s[ni][2] - mnew);
                float p1 = __expf(s[ni][3] - mnew);
                rs += p0 + p1;
                uint2 pp; pp.x = to_tf32(p0); pp.y = to_tf32(p1);
                *(uint2*)&QP[(arow + 8) * 68 + ni * 8 + 2 * tq] = pp;
                o[ni][2] *= alpha; o[ni][3] *= alpha;
            }
            rs += __shfl_xor_sync(0xffffffffu, rs, 1);
            rs += __shfl_xor_sync(0xffffffffu, rs, 2);
            l1 = l1 * alpha + rs;
        }
        // P rows are owned + read only by this warp -> warp-scope sync is enough
        __syncwarp();

        // ---- O += P @ V ----------------------------------------------------
#pragma unroll
        for (int ks = 0; ks < 8; ks++) {
            uint32_t pa[4];
            pa[0] = QP[arow * 68 + ks * 8 + tq];
            pa[1] = QP[(arow + 8) * 68 + ks * 8 + tq];
            pa[2] = QP[arow * 68 + ks * 8 + tq + 4];
            pa[3] = QP[(arow + 8) * 68 + ks * 8 + tq + 4];
#pragma unroll
            for (int ni = 0; ni < 8; ni++) {
                uint32_t b0 = Vs[(ks * 8 + tq) * 72 + ni * 8 + quad];
                uint32_t b1 = Vs[(ks * 8 + tq + 4) * 72 + ni * 8 + quad];
                mma_tf32(o[ni], pa, b0, b1);
            }
        }
    }

    // ---- epilogue ---------------------------------------------------------
    const float inv0 = 1.0f / l0;
    const float inv1 = 1.0f / l1;
    const size_t base0 = ((size_t)(b * SEQ + q0 + arow)) * BDIM + head * HD;
    const size_t base1 = ((size_t)(b * SEQ + q0 + arow + 8)) * BDIM + head * HD;
#pragma unroll
    for (int ni = 0; ni < 8; ni++) {
        const int dd = ni * 8 + 2 * tq;
        float2 v0; v0.x = o[ni][0] * inv0; v0.y = o[ni][1] * inv0;
        float2 v1; v1.x = o[ni][2] * inv1; v1.y = o[ni][3] * inv1;
        *(float2*)&g_att[base0 + dd] = v0;
        *(float2*)&g_att[base1 + dd] = v1;
    }
}

// ---------------------------------------------------------------------------
extern "C" void kernel_launch(void* const* d_in, const int* in_sizes, int n_in,
                              void* d_out, int out_size)
{
    const float* x      = (const float*)d_in[0];
    // d_in[1] = H, d_in[2] = W (unused, fixed 48x48)
    const float* qkv_w  = (const float*)d_in[3];
    const float* proj_w = (const float*)d_in[4];
    const float* proj_b = (const float*)d_in[5];
    float* out = (float*)d_out;

    const int ATTN_SMEM = AT_WORDS * 4;   // 70656 B
    cudaFuncSetAttribute(attn_mma_kernel,
                         cudaFuncAttributeMaxDynamicSharedMemorySize, ATTN_SMEM);

    // GEMM 1 (verified tf32 mma): qkv -> scatter Q/K/V
    dim3 g1(2304 / 128, MTOT / 128);   // 18 x 36
    qkv_mma_kernel<<<g1, 256>>>(x, qkv_w);

    // Flash attention (tf32 mma, 128-row Q tiles, 8 warps)
    dim3 g2(SEQ / 128, BATCH * HEADS); // 18 x 24
    attn_mma_kernel<<<g2, 256, ATTN_SMEM>>>();

    // GEMM 2 (verified tf32 mma): proj + bias
    dim3 g3(BDIM / 128, MTOT / 128);   // 6 x 36
    proj_mma_kernel<<<g3, 256>>>(proj_w, proj_b, out);
}